// round 8
// baseline (speedup 1.0000x reference)
#include <cuda_runtime.h>
#include <stdint.h>

#define BATCH 32
#define NPTS  16384
#define NROT  24
#define IMS   64
#define NPIX  4096
#define NIMG  768
#define TOT   (NIMG * NPIX)            // 3,145,728
#define NBUCK 65                       // 64 py rows + 1 py-OOR bucket
#define CAP   1024
#define ROWW  65                       // 64 px cols + 1 spill col
#define GWIMG (IMS * ROWW)             // 4160 words per image
#define GWTOT (NIMG * GWIMG)
#define SCTA  520                      // 520 CTAs x 4 buckets = 2080

// Winner keys (p+1), stride-65 rows with spill col 64 for px-OOR writes.
// Zero-init at load; unpack resets everything each call.
__device__ unsigned g_win[GWTOT];
__device__ unsigned g_cnt[BATCH * NBUCK];
__device__ unsigned g_buck[BATCH * NBUCK * CAP];

// ---------------------------------------------------------------- kernel 1
__global__ __launch_bounds__(256) void bucket_kernel(const float* __restrict__ xyz)
{
    __shared__ unsigned scnt[NBUCK], sbase[NBUCK];
    int tid = threadIdx.x;
    if (tid < NBUCK) scnt[tid] = 0u;
    __syncthreads();

    int p = blockIdx.x * 256 + tid;
    int b = p >> 14;
    float y = xyz[p * 3 + 1];
    int py = __float2int_rn((y + 2.0f) * 16.0f);   // /0.0625 == *16 exact
    int bk = ((unsigned)py < IMS) ? py : 64;
    unsigned rank = atomicAdd(&scnt[bk], 1u);
    __syncthreads();

    if (tid < NBUCK && scnt[tid])
        sbase[tid] = atomicAdd(&g_cnt[b * NBUCK + tid], scnt[tid]);
    __syncthreads();

    g_buck[(b * NBUCK + bk) * CAP + sbase[bk] + rank] = (unsigned)p;
}

// ---------------------------------------------------------------- kernel 2
__global__ __launch_bounds__(256) void scatter_kernel(const float* __restrict__ xyz,
                                                      const float* __restrict__ rot)
{
    __shared__ unsigned long long s_mx[12], s_mz[12];
    __shared__ unsigned s_red[8];
    int tid = threadIdx.x;
    if (tid < 12) {
        float c0 = rot[(2 * tid) * 9 + 0], c1 = rot[(2 * tid + 1) * 9 + 0];  // m00
        float d0 = rot[(2 * tid) * 9 + 2], d1 = rot[(2 * tid + 1) * 9 + 2];  // m02
        unsigned long long a, bb;
        asm("mov.b64 %0, {%1,%2};" : "=l"(a)  : "f"(c0), "f"(c1));
        asm("mov.b64 %0, {%1,%2};" : "=l"(bb) : "f"(d0), "f"(d1));
        s_mx[tid] = a; s_mz[tid] = bb;
    }
    __syncthreads();
    unsigned long long mx[12], mz[12];
#pragma unroll
    for (int j = 0; j < 12; j++) { mx[j] = s_mx[j]; mz[j] = s_mz[j]; }

    const unsigned long long C16 = 0x4180000041800000ULL;   // (16f,16f)
    const unsigned long long C32 = 0x4200000042000000ULL;   // (32f,32f)

    for (int wk = blockIdx.x; wk < BATCH * NBUCK; wk += SCTA) {
        int b  = wk / NBUCK;
        int bk = wk - b * NBUCK;
        unsigned cnt = g_cnt[wk];
        const unsigned* __restrict__ buck = g_buck + (size_t)wk * CAP;

        if (bk == 64) {
            // py-OOR: masked in every rotation -> pixel(0,0). Block-reduce max
            // key, then one spill-slot atomic per rotation.
            unsigned best = 0u;
            for (unsigned i = tid; i < cnt; i += 256) best = max(best, buck[i] + 1u);
            best = __reduce_max_sync(0xffffffffu, best);
            if ((tid & 31) == 0) s_red[tid >> 5] = best;
            __syncthreads();
            if (tid < NROT) {
                unsigned m = s_red[0];
#pragma unroll
                for (int j = 1; j < 8; j++) m = max(m, s_red[j]);
                if (m) atomicMax(g_win + (size_t)(b * NROT + tid) * GWIMG + 64, m);
            }
            __syncthreads();
            continue;
        }

        unsigned* __restrict__ base = g_win + (size_t)(b * NROT) * GWIMG + bk * ROWW;
        for (unsigned i = tid; i < cnt; i += 256) {
            unsigned p = buck[i];
            unsigned key = p + 1u;
            float x = xyz[p * 3 + 0];
            float z = xyz[p * 3 + 2];
            unsigned long long x2, z2;
            asm("mov.b64 %0, {%1,%2};" : "=l"(x2) : "f"(x), "f"(x));
            asm("mov.b64 %0, {%1,%2};" : "=l"(z2) : "f"(z), "f"(z));
#pragma unroll
            for (int j = 0; j < 12; j++) {
                unsigned long long t2, f2;
                // xr = fma(m02, z, m00*x)  (two rotations per packed op)
                asm("mul.rn.f32x2 %0, %1, %2;"
                    : "=l"(t2) : "l"(mx[j]), "l"(x2));
                asm("fma.rn.f32x2 %0, %1, %2, %3;"
                    : "=l"(t2) : "l"(mz[j]), "l"(z2), "l"(t2));
                // f = fma(xr,16,32) == (xr+2)*16 bit-exactly (pow2 scaling)
                asm("fma.rn.f32x2 %0, %1, %2, %3;"
                    : "=l"(f2) : "l"(t2), "l"(C16), "l"(C32));
                float f0, f1;
                asm("mov.b64 {%0,%1}, %2;" : "=f"(f0), "=f"(f1) : "l"(f2));
                unsigned o0 = min((unsigned)__float2int_rn(f0), 64u);  // OOR->spill
                unsigned o1 = min((unsigned)__float2int_rn(f1), 64u);
                atomicMax(base + (2 * j + 0) * GWIMG + o0, key);
                atomicMax(base + (2 * j + 1) * GWIMG + o1, key);
            }
        }
    }
}

// ---------------------------------------------------------------- kernel 3
__global__ __launch_bounds__(256) void unpack_kernel(const float* __restrict__ xyz,
                                                     const float* __restrict__ rot,
                                                     float* __restrict__ out)
{
    int i = blockIdx.x * 256 + threadIdx.x;
    int img = i >> 12;
    int pix = i & (NPIX - 1);
    int py = pix >> 6;
    int px = pix & 63;
    size_t gi = (size_t)img * GWIMG + py * ROWW + px;
    unsigned w = g_win[gi];
    g_win[gi] = 0u;

    if (pix == 0) {   // merge all 64 spill slots of this image into pixel (0,0)
        unsigned* sp = g_win + (size_t)img * GWIMG + 64;
#pragma unroll 4
        for (int j = 0; j < IMS; j++) {
            unsigned s = sp[j * ROWW];
            if (s) { w = max(w, s); }
            sp[j * ROWW] = 0u;
        }
    }
    if (i < BATCH * NBUCK) g_cnt[i] = 0u;

    float val = 0.0f;
    if (w) {
        unsigned p = w - 1u;
        int r = img - (img / NROT) * NROT;
        float x = xyz[p * 3 + 0];
        float z = xyz[p * 3 + 2];
        float zr = fmaf(rot[r * 9 + 8], z, rot[r * 9 + 6] * x);
        // exact round-to-nearest /10: v/10 is never a float midpoint, so the
        // double product rounds to the correctly-rounded quotient.
        val = (float)((double)zr * 0.1);
    }
    out[i] = val;
}

extern "C" void kernel_launch(void* const* d_in, const int* in_sizes, int n_in,
                              void* d_out, int out_size)
{
    const float* xyz = (const float*)d_in[0];   // [32, 16384, 3] f32
    const float* rot = (const float*)d_in[1];   // [24, 3, 3] f32
    float* out = (float*)d_out;                 // [32, 24, 64, 64] f32

    bucket_kernel<<<(BATCH * NPTS) / 256, 256>>>(xyz);
    scatter_kernel<<<SCTA, 256>>>(xyz, rot);
    unpack_kernel<<<TOT / 256, 256>>>(xyz, rot, out);
}

// round 9
// speedup vs baseline: 1.4209x; 1.4209x over previous
#include <cuda_runtime.h>
#include <stdint.h>

#define BATCH 32
#define NPTS  16384
#define NROT  24
#define IMS   64
#define NPIX  4096
#define NIMG  768
#define TOT   (NIMG * NPIX)            // 3,145,728
#define NBUCK 65                       // 64 py rows + 1 py-OOR bucket
#define CAP   1024                     // max real bucket ~530

// Winner keys (p+1). max key <=> max n within a batch <=> last-write-wins.
// Zero-initialized at load; unpack resets everything each call.
__device__ unsigned g_win[TOT];                    // 12.6 MB
__device__ unsigned g_cnt[BATCH * NBUCK];
__device__ unsigned g_bkey[BATCH * NBUCK * CAP];   // key = p+1
__device__ float2   g_bxz[BATCH * NBUCK * CAP];    // (x, z) payload

// ---------------------------------------------------------------- kernel 1
// Bucket points by (batch, py); py is rotation-invariant (rotation about y).
__global__ __launch_bounds__(256) void bucket_kernel(const float* __restrict__ xyz)
{
    __shared__ unsigned scnt[NBUCK], sbase[NBUCK];
    int tid = threadIdx.x;
    if (tid < NBUCK) scnt[tid] = 0u;
    __syncthreads();

    int p = blockIdx.x * 256 + tid;     // block lies within one batch
    int b = p >> 14;
    float x = xyz[p * 3 + 0];
    float y = xyz[p * 3 + 1];
    float z = xyz[p * 3 + 2];
    int py = __float2int_rn(fmaf(y, 16.0f, 32.0f));  // == rn((y+2)/0.0625)
    int bk = ((unsigned)py < IMS) ? py : 64;         // OOR py -> bucket 64
    unsigned rank = atomicAdd(&scnt[bk], 1u);
    __syncthreads();

    if (tid < NBUCK && scnt[tid])
        sbase[tid] = atomicAdd(&g_cnt[b * NBUCK + tid], scnt[tid]);
    __syncthreads();

    unsigned slot = (b * NBUCK + bk) * CAP + sbase[bk] + rank;
    g_bkey[slot] = (unsigned)p + 1u;
    g_bxz[slot]  = make_float2(x, z);
}

// ---------------------------------------------------------------- kernel 2
// One CTA per (batch, bucket). All lanes share py -> each rotation's 32
// atomics land in one aligned 256B image row (8 coalesced sectors).
__global__ __launch_bounds__(256) void scatter_kernel(const float* __restrict__ rot)
{
    __shared__ float2 srot[NROT];   // (m00, m02) = (c, -s); px needs only these
    __shared__ unsigned s_red[8];
    int tid = threadIdx.x;
    if (tid < NROT) {
        const float* m = rot + tid * 9;
        srot[tid] = make_float2(m[0], m[2]);
    }
    __syncthreads();

    int bk = blockIdx.x % NBUCK;
    int b  = blockIdx.x / NBUCK;
    unsigned cnt = g_cnt[b * NBUCK + bk];
    const unsigned* __restrict__ bkey = g_bkey + (size_t)(b * NBUCK + bk) * CAP;
    const float2*   __restrict__ bxz  = g_bxz  + (size_t)(b * NBUCK + bk) * CAP;
    unsigned* __restrict__ wbase = g_win + (size_t)b * NROT * NPIX;

    if (bk == 64) {
        // py-OOR: masked in every rotation -> pixel (0,0) of all 24 images.
        // Only the max key can win; block-reduce then 24 atomics total.
        unsigned best = 0u;
        for (unsigned i = tid; i < cnt; i += 256) best = max(best, bkey[i]);
        best = __reduce_max_sync(0xffffffffu, best);
        if ((tid & 31) == 0) s_red[tid >> 5] = best;
        __syncthreads();
        if (tid < NROT) {
            unsigned m = s_red[0];
#pragma unroll
            for (int j = 1; j < 8; j++) m = max(m, s_red[j]);
            if (m) atomicMax(wbase + tid * NPIX, m);
        }
        return;
    }

    int rowoff = bk * IMS;
    for (unsigned i = tid; i < cnt; i += 256) {
        unsigned key = bkey[i];
        float2 xz = bxz[i];
#pragma unroll
        for (int r = 0; r < NROT; r++) {
            float2 m = srot[r];
            float xr = fmaf(m.y, xz.y, m.x * xz.x);        // matches XLA fma; 0*y exact
            int px = __float2int_rn(fmaf(xr, 16.0f, 32.0f)); // == rn((xr+2)*16)
            bool in = ((unsigned)px < IMS);
            int pix = in ? (rowoff + px) : 0;              // px-OOR -> pixel 0
            atomicMax(wbase + r * NPIX + pix, key);
        }
    }
}

// ---------------------------------------------------------------- kernel 3
// key -> value: gather (x,z) of the winning point, recompute val with a
// bit-identical FP sequence. Resets all scratch for the next graph replay.
__global__ __launch_bounds__(256) void unpack_kernel(const float* __restrict__ xyz,
                                                     const float* __restrict__ rot,
                                                     float* __restrict__ out)
{
    int i = blockIdx.x * 256 + threadIdx.x;
    unsigned w = g_win[i];
    g_win[i] = 0u;
    if (i < BATCH * NBUCK) g_cnt[i] = 0u;

    float val = 0.0f;
    if (w) {
        unsigned p = w - 1u;
        int img = i >> 12;
        int r = img - (img / NROT) * NROT;
        float x = xyz[p * 3 + 0];
        float z = xyz[p * 3 + 2];
        float zr = fmaf(rot[r * 9 + 8], z, rot[r * 9 + 6] * x);
        // Exact RN division by 10: zr/10 is never a float rounding midpoint,
        // so the double product rounds to the correctly-rounded quotient.
        val = (float)((double)zr * 0.1);
    }
    out[i] = val;
}

extern "C" void kernel_launch(void* const* d_in, const int* in_sizes, int n_in,
                              void* d_out, int out_size)
{
    const float* xyz = (const float*)d_in[0];   // [32, 16384, 3] f32
    const float* rot = (const float*)d_in[1];   // [24, 3, 3] f32
    float* out = (float*)d_out;                 // [32, 24, 64, 64] f32

    bucket_kernel<<<(BATCH * NPTS) / 256, 256>>>(xyz);
    scatter_kernel<<<BATCH * NBUCK, 256>>>(rot);
    unpack_kernel<<<TOT / 256, 256>>>(xyz, rot, out);
}

// round 10
// speedup vs baseline: 2.5545x; 1.7978x over previous
#include <cuda_runtime.h>
#include <stdint.h>

#define BATCH 32
#define NPTS  16384
#define NROT  24
#define IMS   64
#define NPIX  4096
#define NIMG  768
#define TOT   (NIMG * NPIX)            // 3,145,728
#define NBUCK 65                       // 64 py rows + 1 py-OOR bucket
#define CAP   1024                     // max real bucket ~530

// Winner keys (p+1). max key <=> max n within a batch <=> last-write-wins.
// Zero-initialized at load; unpack resets everything each call.
__device__ __align__(16) unsigned g_win[TOT];      // 12.6 MB, L2-resident
__device__ unsigned g_cnt[BATCH * NBUCK];
__device__ unsigned g_buck[BATCH * NBUCK * CAP];   // point ids

// ---------------------------------------------------------------- kernel 1
// Bucket points by (batch, py). py is rotation-invariant (rotation about y).
__global__ __launch_bounds__(256) void bucket_kernel(const float* __restrict__ xyz)
{
    __shared__ unsigned scnt[NBUCK], sbase[NBUCK];
    int tid = threadIdx.x;
    if (tid < NBUCK) scnt[tid] = 0u;
    __syncthreads();

    int p = blockIdx.x * 256 + tid;     // block lies within one batch
    int b = p >> 14;
    float y = xyz[p * 3 + 1];
    int py = __float2int_rn(fmaf(y, 16.0f, 32.0f));  // == rn((y+2)/0.0625), exact
    int bk = ((unsigned)py < IMS) ? py : 64;         // OOR py -> bucket 64
    unsigned rank = atomicAdd(&scnt[bk], 1u);
    __syncthreads();

    if (tid < NBUCK && scnt[tid])
        sbase[tid] = atomicAdd(&g_cnt[b * NBUCK + tid], scnt[tid]);
    __syncthreads();

    g_buck[(b * NBUCK + bk) * CAP + sbase[bk] + rank] = (unsigned)p;
}

// ---------------------------------------------------------------- kernel 2
// One CTA per (batch, bucket). bid remapped so the biggest (center-row)
// buckets launch first: i-th centrality rank -> row 32,31,33,30,34,...
// All lanes of a warp share py -> each rotation's 32 atomics hit one aligned
// 256B image row (coalesced L2 sectors).
__global__ __launch_bounds__(256) void scatter_kernel(const float* __restrict__ xyz,
                                                      const float* __restrict__ rot)
{
    __shared__ float2 srot[NROT];   // (m00, m02) = (c, -s)
    __shared__ unsigned s_red[8];
    int tid = threadIdx.x;
    if (tid < NROT) {
        const float* m = rot + tid * 9;
        srot[tid] = make_float2(m[0], m[2]);
    }
    __syncthreads();

    int bid = blockIdx.x;
    int b, bk;
    if (bid < BATCH * IMS) {
        b = bid & 31;                               // 32 same-size CTAs adjacent
        int i = bid >> 5;                           // centrality rank 0..63
        bk = (i & 1) ? (32 - ((i + 1) >> 1)) : (32 + (i >> 1));
    } else {
        b = bid - BATCH * IMS;                      // py-OOR buckets last
        bk = 64;
    }

    unsigned cnt = g_cnt[b * NBUCK + bk];
    const unsigned* __restrict__ buck = g_buck + (size_t)(b * NBUCK + bk) * CAP;
    unsigned* __restrict__ wbase = g_win + (size_t)b * NROT * NPIX;

    if (bk == 64) {
        // py-OOR: masked in every rotation -> pixel (0,0) of all 24 images.
        // Only the max key can win; block-reduce then 24 atomics total.
        unsigned best = 0u;
        for (unsigned i = tid; i < cnt; i += 256) best = max(best, buck[i] + 1u);
        best = __reduce_max_sync(0xffffffffu, best);
        if ((tid & 31) == 0) s_red[tid >> 5] = best;
        __syncthreads();
        if (tid < NROT) {
            unsigned m = s_red[0];
#pragma unroll
            for (int j = 1; j < 8; j++) m = max(m, s_red[j]);
            if (m) atomicMax(wbase + tid * NPIX, m);
        }
        return;
    }

    int rowoff = bk * IMS;
    for (unsigned i = tid; i < cnt; i += 256) {
        unsigned p = buck[i];
        unsigned key = p + 1u;
        float x = xyz[p * 3 + 0];
        float z = xyz[p * 3 + 2];
#pragma unroll
        for (int r = 0; r < NROT; r++) {
            float2 m = srot[r];
            float xr = fmaf(m.y, z, m.x * x);            // matches XLA fma; 0*y exact
            int px = __float2int_rn(fmaf(xr, 16.0f, 32.0f)); // == rn((xr+2)*16)
            int pix = ((unsigned)px < IMS) ? (rowoff + px) : 0; // px-OOR -> pixel 0
            atomicMax(wbase + r * NPIX + pix, key);
        }
    }
}

// ---------------------------------------------------------------- kernel 3
// 4 pixels per thread: uint4 winner load + reset, float4 output store.
// Winner key -> gather (x,z), recompute val with bit-identical FP sequence.
__global__ __launch_bounds__(256) void unpack_kernel(const float* __restrict__ xyz,
                                                     const float* __restrict__ rot,
                                                     float* __restrict__ out)
{
    int t = blockIdx.x * 256 + threadIdx.x;   // [0, TOT/4)
    int i = t * 4;
    uint4 w4 = *reinterpret_cast<uint4*>(g_win + i);
    *reinterpret_cast<uint4*>(g_win + i) = make_uint4(0u, 0u, 0u, 0u);
    if (t < BATCH * NBUCK) g_cnt[t] = 0u;

    int img = i >> 12;                        // 4 consecutive pixels share image
    int r = img - (img / NROT) * NROT;
    float m20 = rot[r * 9 + 6];
    float m22 = rot[r * 9 + 8];

    unsigned wk[4] = {w4.x, w4.y, w4.z, w4.w};
    float v[4];
#pragma unroll
    for (int j = 0; j < 4; j++) {
        float val = 0.0f;
        unsigned w = wk[j];
        if (w) {
            unsigned p = w - 1u;
            float x = xyz[p * 3 + 0];
            float z = xyz[p * 3 + 2];
            float zr = fmaf(m22, z, m20 * x);
            // Exact RN /10: zr/10 is never a float rounding midpoint, so the
            // double product rounds to the correctly-rounded float quotient.
            val = (float)((double)zr * 0.1);
        }
        v[j] = val;
    }
    *reinterpret_cast<float4*>(out + i) = make_float4(v[0], v[1], v[2], v[3]);
}

extern "C" void kernel_launch(void* const* d_in, const int* in_sizes, int n_in,
                              void* d_out, int out_size)
{
    const float* xyz = (const float*)d_in[0];   // [32, 16384, 3] f32
    const float* rot = (const float*)d_in[1];   // [24, 3, 3] f32
    float* out = (float*)d_out;                 // [32, 24, 64, 64] f32

    bucket_kernel<<<(BATCH * NPTS) / 256, 256>>>(xyz);
    scatter_kernel<<<BATCH * NBUCK, 256>>>(xyz, rot);
    unpack_kernel<<<TOT / 4 / 256, 256>>>(xyz, rot, out);
}